// round 4
// baseline (speedup 1.0000x reference)
#include <cuda_runtime.h>

// VoxelGrid trilinear interpolation, 8-corner packed + 256-bit gathers +
// explicit L2 residency management:
//   - packed grid written with L2::evict_last (sticky in 126MB L2)
//   - gathers read with L2::evict_last
//   - streaming x reads via __ldcs (evict-first), outputs via __stcs
//
// Inputs: d_in[0]=x float32[N,3], d_in[1]=grid float32[200,200,50,1]
// Output: out[0:N]=sigma, out[N:2N]=alpha(=0)

#define SX 200
#define SY 200
#define SZ 50
#define NCELLS (SX * SY * SZ)     // 2,000,000
#define STRIDE_X (SY * SZ)        // 10000
#define STRIDE_Y (SZ)             // 50

struct __align__(32) Cell8 {
    float4 a;   // x0 plane: (v000, v001, v010, v011)
    float4 b;   // x1 plane: (v100, v101, v110, v111)
};

__device__ Cell8 g_packed8[NCELLS];   // 64 MB static scratch (allowed)

__device__ __forceinline__ void stg256_evict_last(Cell8* p, const float4& a, const float4& b)
{
    asm volatile(
        "st.global.L2::evict_last.v8.f32 [%0], "
        "{%1, %2, %3, %4, %5, %6, %7, %8};"
        :: "l"(p),
           "f"(a.x), "f"(a.y), "f"(a.z), "f"(a.w),
           "f"(b.x), "f"(b.y), "f"(b.z), "f"(b.w)
        : "memory");
}

__global__ __launch_bounds__(256)
void pack_kernel(const float* __restrict__ g)
{
    const int idx = blockIdx.x * blockDim.x + threadIdx.x;
    if (idx >= NCELLS) return;
    const int z = idx % SZ;
    const int y = (idx / SZ) % SY;
    const int x = idx / (SZ * SY);
    const int z1 = min(z + 1, SZ - 1);
    const int y1 = min(y + 1, SY - 1);
    const int x1 = min(x + 1, SX - 1);

    const float* b0 = g + x  * STRIDE_X;
    const float* b1 = g + x1 * STRIDE_X;

    float4 a, b;
    a.x = __ldg(b0 + y  * STRIDE_Y + z);
    a.y = __ldg(b0 + y  * STRIDE_Y + z1);
    a.z = __ldg(b0 + y1 * STRIDE_Y + z);
    a.w = __ldg(b0 + y1 * STRIDE_Y + z1);
    b.x = __ldg(b1 + y  * STRIDE_Y + z);
    b.y = __ldg(b1 + y  * STRIDE_Y + z1);
    b.z = __ldg(b1 + y1 * STRIDE_Y + z);
    b.w = __ldg(b1 + y1 * STRIDE_Y + z1);
    stg256_evict_last(&g_packed8[idx], a, b);
}

// One 256-bit non-coherent load with L2 evict_last (keep packed grid resident).
__device__ __forceinline__ void ldg256(const Cell8* p, float4& q0, float4& q1)
{
    asm volatile(
        "ld.global.nc.L2::evict_last.v8.f32 "
        "{%0, %1, %2, %3, %4, %5, %6, %7}, [%8];"
        : "=f"(q0.x), "=f"(q0.y), "=f"(q0.z), "=f"(q0.w),
          "=f"(q1.x), "=f"(q1.y), "=f"(q1.z), "=f"(q1.w)
        : "l"(p));
}

__global__ __launch_bounds__(256)
void voxelgrid_kernel(const float* __restrict__ x,
                      float* __restrict__ out,
                      int n)
{
    const int t = blockIdx.x * blockDim.x + threadIdx.x;
    const long long base = (long long)t * 4;
    if (base >= n) return;

    // 4 points = 12 contiguous floats via 3 streaming float4 loads
    // (evict-first: don't let point data evict the packed grid from L2).
    const float4* xv = reinterpret_cast<const float4*>(x + base * 3);
    const float4 va = __ldcs(xv + 0);
    const float4 vb = __ldcs(xv + 1);
    const float4 vc = __ldcs(xv + 2);

    const float px[4] = {va.x, va.w, vb.z, vc.y};
    const float py[4] = {va.y, vb.x, vb.w, vc.z};
    const float pz[4] = {va.z, vb.y, vc.x, vc.w};

    float sig[4];

    #pragma unroll
    for (int p = 0; p < 4; ++p) {
        const float ix = (px[p] + 4.0f) * 25.0f;
        const float iy = (py[p] + 4.0f) * 25.0f;
        const float iz = (pz[p] + 1.0f) * 25.0f;

        const bool valid =
            (ix >= 0.0f) & (ix <= (float)(SX - 1)) &
            (iy >= 0.0f) & (iy <= (float)(SY - 1)) &
            (iz >= 0.0f) & (iz <= (float)(SZ - 1));

        const float fx = floorf(ix);
        const float fy = floorf(iy);
        const float fz = floorf(iz);

        const int x0 = min(max((int)fx, 0), SX - 1);
        const int y0 = min(max((int)fy, 0), SY - 1);
        const int z0 = min(max((int)fz, 0), SZ - 1);

        const float tx = ix - fx;
        const float ty = iy - fy;
        const float tz = iz - fz;
        const float sx0 = 1.0f - tx, sy0 = 1.0f - ty, sz0 = 1.0f - tz;

        // Single 32B gather: all 8 corners.
        float4 v0, v1;
        ldg256(&g_packed8[x0 * STRIDE_X + y0 * STRIDE_Y + z0], v0, v1);

        const float w00 = sy0 * sz0;
        const float w01 = sy0 * tz;
        const float w10 = ty  * sz0;
        const float w11 = ty  * tz;

        float inner0 = v0.x * w00;
        inner0 = fmaf(v0.y, w01, inner0);
        inner0 = fmaf(v0.z, w10, inner0);
        inner0 = fmaf(v0.w, w11, inner0);

        float inner1 = v1.x * w00;
        inner1 = fmaf(v1.y, w01, inner1);
        inner1 = fmaf(v1.z, w10, inner1);
        inner1 = fmaf(v1.w, w11, inner1);

        const float acc = fmaf(sx0, inner0, tx * inner1);
        sig[p] = valid ? acc : 0.0f;
    }

    // Streaming stores (evict-first): don't pollute L2 against packed grid.
    float4* so = reinterpret_cast<float4*>(out + base);
    __stcs(so, make_float4(sig[0], sig[1], sig[2], sig[3]));
    float4* ao = reinterpret_cast<float4*>(out + (long long)n + base);
    __stcs(ao, make_float4(0.0f, 0.0f, 0.0f, 0.0f));
}

extern "C" void kernel_launch(void* const* d_in, const int* in_sizes, int n_in,
                              void* d_out, int out_size)
{
    const float* x    = (const float*)d_in[0];
    const float* grid = (const float*)d_in[1];
    float* out = (float*)d_out;

    const int n = in_sizes[0] / 3;

    const int pack_threads = 256;
    const int pack_blocks = (NCELLS + pack_threads - 1) / pack_threads;
    pack_kernel<<<pack_blocks, pack_threads>>>(grid);

    const int threads = 256;
    const int pts_per_thread = 4;
    const int blocks = (n + threads * pts_per_thread - 1) / (threads * pts_per_thread);
    voxelgrid_kernel<<<blocks, threads>>>(x, out, n);
}

// round 6
// speedup vs baseline: 1.2532x; 1.2532x over previous
#include <cuda_runtime.h>
#include <cuda_fp16.h>
#include <cstdint>

// VoxelGrid trilinear interpolation: 8 corners packed as fp16 (16B/cell,
// 32 MB total -> L2-resident under plain LRU), ONE LDG.128 gather per point.
//
// Stage 1 (pack): Cell8h[x][y][z] = fp16 x 8 corners, clamps identical to
//   reference (i1 = min(i0+1, size-1)).
// Stage 2 (query): 1 gather + fp32 weight math.
//
// Inputs: d_in[0]=x float32[N,3], d_in[1]=grid float32[200,200,50,1]
// Output: out[0:N]=sigma, out[N:2N]=alpha(=0)

#define SX 200
#define SY 200
#define SZ 50
#define NCELLS (SX * SY * SZ)     // 2,000,000
#define STRIDE_X (SY * SZ)        // 10000
#define STRIDE_Y (SZ)             // 50

// 16-byte cell: ((v000,v001),(v010,v011),(v100,v101),(v110,v111)) as half2.
__device__ uint4 g_packed_h[NCELLS];   // 32 MB static scratch

__device__ __forceinline__ unsigned int pack_h2(float lo, float hi)
{
    __half2 h = __floats2half2_rn(lo, hi);
    return *reinterpret_cast<unsigned int*>(&h);
}

__global__ __launch_bounds__(256)
void pack_kernel(const float* __restrict__ g)
{
    const int idx = blockIdx.x * blockDim.x + threadIdx.x;
    if (idx >= NCELLS) return;
    const int z = idx % SZ;
    const int y = (idx / SZ) % SY;
    const int x = idx / (SZ * SY);
    const int z1 = min(z + 1, SZ - 1);
    const int y1 = min(y + 1, SY - 1);
    const int x1 = min(x + 1, SX - 1);

    const float* b0 = g + x  * STRIDE_X;
    const float* b1 = g + x1 * STRIDE_X;

    const float v000 = __ldg(b0 + y  * STRIDE_Y + z);
    const float v001 = __ldg(b0 + y  * STRIDE_Y + z1);
    const float v010 = __ldg(b0 + y1 * STRIDE_Y + z);
    const float v011 = __ldg(b0 + y1 * STRIDE_Y + z1);
    const float v100 = __ldg(b1 + y  * STRIDE_Y + z);
    const float v101 = __ldg(b1 + y  * STRIDE_Y + z1);
    const float v110 = __ldg(b1 + y1 * STRIDE_Y + z);
    const float v111 = __ldg(b1 + y1 * STRIDE_Y + z1);

    uint4 c;
    c.x = pack_h2(v000, v001);
    c.y = pack_h2(v010, v011);
    c.z = pack_h2(v100, v101);
    c.w = pack_h2(v110, v111);
    g_packed_h[idx] = c;
}

__global__ __launch_bounds__(256)
void voxelgrid_kernel(const float* __restrict__ x,
                      float* __restrict__ out,
                      int n)
{
    const int t = blockIdx.x * blockDim.x + threadIdx.x;
    const long long base = (long long)t * 4;
    if (base >= n) return;

    // 4 points = 12 contiguous floats, streaming loads (evict-first).
    const float4* xv = reinterpret_cast<const float4*>(x + base * 3);
    const float4 va = __ldcs(xv + 0);
    const float4 vb = __ldcs(xv + 1);
    const float4 vc = __ldcs(xv + 2);

    const float px[4] = {va.x, va.w, vb.z, vc.y};
    const float py[4] = {va.y, vb.x, vb.w, vc.z};
    const float pz[4] = {va.z, vb.y, vc.x, vc.w};

    float sig[4];

    #pragma unroll
    for (int p = 0; p < 4; ++p) {
        const float ix = (px[p] + 4.0f) * 25.0f;
        const float iy = (py[p] + 4.0f) * 25.0f;
        const float iz = (pz[p] + 1.0f) * 25.0f;

        const bool valid =
            (ix >= 0.0f) & (ix <= (float)(SX - 1)) &
            (iy >= 0.0f) & (iy <= (float)(SY - 1)) &
            (iz >= 0.0f) & (iz <= (float)(SZ - 1));

        const float fx = floorf(ix);
        const float fy = floorf(iy);
        const float fz = floorf(iz);

        const int x0 = min(max((int)fx, 0), SX - 1);
        const int y0 = min(max((int)fy, 0), SY - 1);
        const int z0 = min(max((int)fz, 0), SZ - 1);

        const float tx = ix - fx;
        const float ty = iy - fy;
        const float tz = iz - fz;
        const float sx0 = 1.0f - tx, sy0 = 1.0f - ty, sz0 = 1.0f - tz;

        // Single 16B gather: all 8 corners (fp16).
        const uint4 q = __ldg(&g_packed_h[x0 * STRIDE_X + y0 * STRIDE_Y + z0]);
        const float2 c00 = __half22float2(*reinterpret_cast<const __half2*>(&q.x));
        const float2 c01 = __half22float2(*reinterpret_cast<const __half2*>(&q.y));
        const float2 c10 = __half22float2(*reinterpret_cast<const __half2*>(&q.z));
        const float2 c11 = __half22float2(*reinterpret_cast<const __half2*>(&q.w));

        const float w00 = sy0 * sz0;
        const float w01 = sy0 * tz;
        const float w10 = ty  * sz0;
        const float w11 = ty  * tz;

        float inner0 = c00.x * w00;
        inner0 = fmaf(c00.y, w01, inner0);
        inner0 = fmaf(c01.x, w10, inner0);
        inner0 = fmaf(c01.y, w11, inner0);

        float inner1 = c10.x * w00;
        inner1 = fmaf(c10.y, w01, inner1);
        inner1 = fmaf(c11.x, w10, inner1);
        inner1 = fmaf(c11.y, w11, inner1);

        const float acc = fmaf(sx0, inner0, tx * inner1);
        sig[p] = valid ? acc : 0.0f;
    }

    // Streaming stores (evict-first).
    float4* so = reinterpret_cast<float4*>(out + base);
    __stcs(so, make_float4(sig[0], sig[1], sig[2], sig[3]));
    float4* ao = reinterpret_cast<float4*>(out + (long long)n + base);
    __stcs(ao, make_float4(0.0f, 0.0f, 0.0f, 0.0f));
}

extern "C" void kernel_launch(void* const* d_in, const int* in_sizes, int n_in,
                              void* d_out, int out_size)
{
    const float* x    = (const float*)d_in[0];
    const float* grid = (const float*)d_in[1];
    float* out = (float*)d_out;

    const int n = in_sizes[0] / 3;

    const int pack_threads = 256;
    const int pack_blocks = (NCELLS + pack_threads - 1) / pack_threads;
    pack_kernel<<<pack_blocks, pack_threads>>>(grid);

    const int threads = 256;
    const int pts_per_thread = 4;
    const int blocks = (n + threads * pts_per_thread - 1) / (threads * pts_per_thread);
    voxelgrid_kernel<<<blocks, threads>>>(x, out, n);
}